// round 5
// baseline (speedup 1.0000x reference)
#include <cuda_runtime.h>

// Problem constants
constexpr int NB = 32;    // batch
constexpr int NT = 1024;  // tokens (32x32)
constexpr int NF = 768;   // features
constexpr int NS = 16;    // splits per batch in pass C
constexpr int TOK_PER_BLK  = NT / NS;       // 64 tokens per kC block
constexpr int TOK_PER_WARP = TOK_PER_BLK/8; // 8 tokens per warp
constexpr int BLK_PER_BATCH_A = NT / 8;     // 128 kA blocks per batch

// Scratch (device globals — no allocations allowed; zero-init at load,
// counters self-reset each launch so graph replays stay deterministic)
__device__ float g_rnorm[NB * NT];
__device__ float g_p1[NB * NT];
__device__ float g_q[NB * NF];
__device__ float g_d0[NB * NS];
__device__ float g_d1[NB * NS];
__device__ float g_u [NB * NS];
__device__ unsigned g_cntA[NB];
__device__ unsigned g_cntC;

// ---------------------------------------------------------------------------
// Kernel A: one warp per token -> rnorm, p1. The last-finishing block of each
// batch additionally does the per-batch argmax (first-max tiebreak, matching
// jnp.argmax) and writes q = tok[idx] * rnorm[idx].
// ---------------------------------------------------------------------------
__global__ __launch_bounds__(256) void kA(const float* __restrict__ x,
                                          const float* __restrict__ fc_w,
                                          const float* __restrict__ fc_b) {
    const int warp = threadIdx.x >> 5;
    const int lane = threadIdx.x & 31;
    const int g = blockIdx.x * 8 + warp;          // global token id
    const int b = blockIdx.x / BLK_PER_BATCH_A;   // batch of this block

    const float4* tok = reinterpret_cast<const float4*>(x + (size_t)g * NF);
    const float4* w0  = reinterpret_cast<const float4*>(fc_w);
    const float4* w1  = reinterpret_cast<const float4*>(fc_w + NF);

    float nrm = 0.f, d0 = 0.f, d1 = 0.f;
#pragma unroll
    for (int i = 0; i < 6; i++) {
        float4 v = tok[lane + 32 * i];
        float4 a = __ldg(&w0[lane + 32 * i]);
        float4 c = __ldg(&w1[lane + 32 * i]);
        nrm += v.x * v.x + v.y * v.y + v.z * v.z + v.w * v.w;
        d0  += v.x * a.x + v.y * a.y + v.z * a.z + v.w * a.w;
        d1  += v.x * c.x + v.y * c.y + v.z * c.z + v.w * c.w;
    }
#pragma unroll
    for (int o = 16; o; o >>= 1) {
        nrm += __shfl_xor_sync(0xffffffffu, nrm, o);
        d0  += __shfl_xor_sync(0xffffffffu, d0, o);
        d1  += __shfl_xor_sync(0xffffffffu, d1, o);
    }
    if (lane == 0) {
        g_rnorm[g] = rsqrtf(nrm);
        float l0 = d0 + fc_b[0];
        float l1 = d1 + fc_b[1];
        g_p1[g] = 1.f / (1.f + expf(l0 - l1));
        __threadfence();   // make this warp's writes device-visible
    }
    __syncthreads();

    // Last block of this batch does argmax + q write
    __shared__ unsigned s_last;
    if (threadIdx.x == 0)
        s_last = atomicAdd(&g_cntA[b], 1u);
    __syncthreads();
    if (s_last != BLK_PER_BATCH_A - 1) return;
    __threadfence();  // acquire: see all other blocks' p1/rnorm writes

    // argmax over 1024 p1 values with 256 threads (4 candidates each).
    // Comparator (v>best)||(v==best && i<besti) => global first-max.
    float bestv = -1.f; int besti = 0;
#pragma unroll
    for (int k = 0; k < 4; k++) {
        const int t = threadIdx.x + 256 * k;
        const float v = g_p1[b * NT + t];
        if (v > bestv || (v == bestv && t < besti)) { bestv = v; besti = t; }
    }
#pragma unroll
    for (int o = 16; o; o >>= 1) {
        float v2 = __shfl_xor_sync(0xffffffffu, bestv, o);
        int   i2 = __shfl_xor_sync(0xffffffffu, besti, o);
        if (v2 > bestv || (v2 == bestv && i2 < besti)) { bestv = v2; besti = i2; }
    }
    __shared__ float swv[8];
    __shared__ int   swi[8];
    if (lane == 0) { swv[warp] = bestv; swi[warp] = besti; }
    __syncthreads();
    __shared__ int s_idx;
    if (threadIdx.x == 0) {
        float bv = swv[0]; int bi = swi[0];
#pragma unroll
        for (int w = 1; w < 8; w++)
            if (swv[w] > bv || (swv[w] == bv && swi[w] < bi)) { bv = swv[w]; bi = swi[w]; }
        s_idx = bi;
        g_cntA[b] = 0;  // reset for next graph replay
    }
    __syncthreads();
    const int idx = s_idx;
    const float rn = g_rnorm[b * NT + idx];
    const float* qt = x + ((size_t)b * NT + idx) * NF;
    for (int f = threadIdx.x; f < NF; f += 256)
        g_q[b * NF + f] = qt[f] * rn;
}

// ---------------------------------------------------------------------------
// Kernel C: streaming weighted-sum pass. grid = (NS, NB), 256 threads.
// s = q.tok * rnorm_t ; u = exp(s)*p1_t ; accumulate u*tok in registers,
// project onto fc_final_w -> 3 scalars per block. Last-finishing block of
// the whole grid reduces all splits (fixed order) and writes the output.
// ---------------------------------------------------------------------------
__global__ __launch_bounds__(256) void kC(const float* __restrict__ x,
                                          const float* __restrict__ fc_final_w,
                                          const float* __restrict__ fc_final_b,
                                          float* __restrict__ out) {
    const int b    = blockIdx.y;
    const int sp   = blockIdx.x;
    const int warp = threadIdx.x >> 5;
    const int lane = threadIdx.x & 31;

    __shared__ float4 q4s[NF / 4];
    __shared__ float  s0[8], s1[8], su[8];

    const float4* q4 = reinterpret_cast<const float4*>(g_q + b * NF);
    for (int i = threadIdx.x; i < NF / 4; i += 256) q4s[i] = q4[i];
    __syncthreads();

    float4 acc[6];
#pragma unroll
    for (int i = 0; i < 6; i++) acc[i] = make_float4(0.f, 0.f, 0.f, 0.f);
    float u_sum = 0.f;

    const int t0 = sp * TOK_PER_BLK + warp * TOK_PER_WARP;
#pragma unroll 2
    for (int tt = 0; tt < TOK_PER_WARP; tt++) {
        const int t = t0 + tt;
        const float rn = g_rnorm[b * NT + t];
        const float p1 = g_p1[b * NT + t];
        const float4* tok = reinterpret_cast<const float4*>(x + ((size_t)b * NT + t) * NF);
        float4 v[6];
        float s = 0.f;
#pragma unroll
        for (int i = 0; i < 6; i++) {
            v[i] = tok[lane + 32 * i];
            float4 q = q4s[lane + 32 * i];
            s += v[i].x * q.x + v[i].y * q.y + v[i].z * q.z + v[i].w * q.w;
        }
#pragma unroll
        for (int o = 16; o; o >>= 1) s += __shfl_xor_sync(0xffffffffu, s, o);
        const float u = expf(s * rn) * p1;   // lane-replicated
        u_sum += u;
#pragma unroll
        for (int i = 0; i < 6; i++) {
            acc[i].x += u * v[i].x;
            acc[i].y += u * v[i].y;
            acc[i].z += u * v[i].z;
            acc[i].w += u * v[i].w;
        }
    }

    // Project accumulators onto fc_final_w
    const float4* fw0 = reinterpret_cast<const float4*>(fc_final_w);
    const float4* fw1 = reinterpret_cast<const float4*>(fc_final_w + NF);
    float d0 = 0.f, d1 = 0.f;
#pragma unroll
    for (int i = 0; i < 6; i++) {
        float4 a = __ldg(&fw0[lane + 32 * i]);
        float4 c = __ldg(&fw1[lane + 32 * i]);
        d0 += acc[i].x * a.x + acc[i].y * a.y + acc[i].z * a.z + acc[i].w * a.w;
        d1 += acc[i].x * c.x + acc[i].y * c.y + acc[i].z * c.z + acc[i].w * c.w;
    }
#pragma unroll
    for (int o = 16; o; o >>= 1) {
        d0 += __shfl_xor_sync(0xffffffffu, d0, o);
        d1 += __shfl_xor_sync(0xffffffffu, d1, o);
    }
    if (lane == 0) { s0[warp] = d0; s1[warp] = d1; su[warp] = u_sum; }
    __syncthreads();

    __shared__ unsigned s_last;
    if (threadIdx.x == 0) {
        float D0 = 0.f, D1 = 0.f, U = 0.f;
#pragma unroll
        for (int w = 0; w < 8; w++) { D0 += s0[w]; D1 += s1[w]; U += su[w]; }
        g_d0[b * NS + sp] = D0;
        g_d1[b * NS + sp] = D1;
        g_u [b * NS + sp] = U;
        __threadfence();
        s_last = atomicAdd(&g_cntC, 1u);
    }
    __syncthreads();
    if (s_last != (unsigned)(NB * NS - 1)) return;
    __threadfence();  // acquire all blocks' partials

    // Final reduce: threads 0..31 each own one batch; fixed summation order.
    if (threadIdx.x < NB) {
        const int bb = threadIdx.x;
        float D0 = 0.f, D1 = 0.f, U = 0.f;
#pragma unroll
        for (int s = 0; s < NS; s++) {
            D0 += g_d0[bb * NS + s];
            D1 += g_d1[bb * NS + s];
            U  += g_u [bb * NS + s];
        }
        const float invU = 1.f / U;
        out[bb * 2 + 0] = D0 * invU + fc_final_b[0];
        out[bb * 2 + 1] = D1 * invU + fc_final_b[1];
    }
    if (threadIdx.x == 0) g_cntC = 0;  // reset for next replay
}

// ---------------------------------------------------------------------------
extern "C" void kernel_launch(void* const* d_in, const int* in_sizes, int n_in,
                              void* d_out, int out_size) {
    const float* x          = (const float*)d_in[0];
    const float* fc_w       = (const float*)d_in[1];
    const float* fc_b       = (const float*)d_in[2];
    const float* fc_final_w = (const float*)d_in[3];
    const float* fc_final_b = (const float*)d_in[4];
    float* out = (float*)d_out;

    kA<<<NB * NT / 8, 256>>>(x, fc_w, fc_b);
    dim3 gridC(NS, NB);
    kC<<<gridC, 256>>>(x, fc_final_w, fc_final_b, out);
}